// round 6
// baseline (speedup 1.0000x reference)
#include <cuda_runtime.h>
#include <cstdint>

// Problem constants (fixed by the reference)
#define B_ 32
#define D_ 64
#define T_ 4096
#define K_ 512
#define N_ (B_ * T_)        // 131072 tokens
#define NQ_ (B_ * D_ * T_)  // 8388608 quantized elements
#define CAP_ 40

// Scratch (device globals: no allocation allowed)
__device__ unsigned int g_maxz_bits;          // max |z| as float bits
__device__ unsigned int g_maxc_bits;          // max |codebook| as float bits
__device__ int          g_smaxc;              // max_k sum|c_hat|
__device__ float        g_cbnorm[K_];         // exact fp32 row norms
__device__ int          g_cnint[K_];          // cn / (2 s_z s_c), rounded
__device__ __align__(16) int g_cbimg[K_ * 16];// packed int8 codebook rows
__device__ float        g_partial[256];       // per-block loss partials
__device__ unsigned int g_count;              // finalize ticket

// ---------------------------------------------------------------------------
// Exact fp32 distance — bitwise round-0 formula (verified rel_err = 0.0):
// dist = fl( fl(A + cn_k) - fl(2 * dot) ), dot via 4 stride-4 fmaf chains.
// ---------------------------------------------------------------------------
__device__ __forceinline__ float exact_dist(const float* zr, float A,
                                            const float* __restrict__ cb, int k) {
    const float4* cp = reinterpret_cast<const float4*>(cb + (size_t)k * D_);
    float s0 = 0.f, s1 = 0.f, s2 = 0.f, s3 = 0.f;
#pragma unroll
    for (int i = 0; i < 16; ++i) {
        float4 c = __ldg(cp + i);
        s0 = fmaf(zr[4 * i + 0], c.x, s0);
        s1 = fmaf(zr[4 * i + 1], c.y, s1);
        s2 = fmaf(zr[4 * i + 2], c.z, s2);
        s3 = fmaf(zr[4 * i + 3], c.w, s3);
    }
    float dot = __fadd_rn(__fadd_rn(s0, s1), __fadd_rn(s2, s3));
    float cn  = __ldg(&g_cbnorm[k]);
    return __fadd_rn(__fadd_rn(A, cn), -__fmul_rn(2.0f, dot));
}

// ---------------------------------------------------------------------------
// prep 0: global max |z|
// ---------------------------------------------------------------------------
__global__ void prep_z_kernel(const float* __restrict__ z) {
    const float4* z4 = reinterpret_cast<const float4*>(z);
    float m = 0.0f;
    for (int j = blockIdx.x * blockDim.x + threadIdx.x; j < NQ_ / 4;
         j += gridDim.x * blockDim.x) {
        float4 v = z4[j];
        m = fmaxf(m, fmaxf(fmaxf(fabsf(v.x), fabsf(v.y)),
                           fmaxf(fabsf(v.z), fabsf(v.w))));
    }
#pragma unroll
    for (int o = 16; o > 0; o >>= 1) m = fmaxf(m, __shfl_xor_sync(0xffffffffu, m, o));
    if ((threadIdx.x & 31) == 0) atomicMax(&g_maxz_bits, __float_as_uint(m));
}

// prep 1: exact norms (canonical fmaf order) + max |c|
__global__ void prep_cb1_kernel(const float* __restrict__ cb) {
    int k = blockIdx.x * blockDim.x + threadIdx.x;
    if (k < K_) {
        const float* r = cb + k * D_;
        float a = 0.0f, mx = 0.0f;
#pragma unroll
        for (int i = 0; i < D_; ++i) {
            a = fmaf(r[i], r[i], a);
            mx = fmaxf(mx, fabsf(r[i]));
        }
        g_cbnorm[k] = a;
        atomicMax(&g_maxc_bits, __float_as_uint(mx));
    }
}

// prep 2: int8 image, sum|c_hat| max, cn_int (needs maxz & maxc)
__global__ void prep_cb2_kernel(const float* __restrict__ cb) {
    int k = blockIdx.x * blockDim.x + threadIdx.x;
    if (k >= K_) return;
    const float maxz = __uint_as_float(g_maxz_bits);
    const float maxc = __uint_as_float(g_maxc_bits);
    const float inv_sc = (maxc > 0.0f) ? 127.0f / maxc : 0.0f;
    const float* r = cb + k * D_;
    int sa = 0;
#pragma unroll
    for (int j = 0; j < 16; ++j) {
        int b0 = min(127, max(-127, __float2int_rn(r[4 * j + 0] * inv_sc)));
        int b1 = min(127, max(-127, __float2int_rn(r[4 * j + 1] * inv_sc)));
        int b2 = min(127, max(-127, __float2int_rn(r[4 * j + 2] * inv_sc)));
        int b3 = min(127, max(-127, __float2int_rn(r[4 * j + 3] * inv_sc)));
        sa += abs(b0) + abs(b1) + abs(b2) + abs(b3);
        g_cbimg[k * 16 + j] = (b0 & 0xFF) | ((b1 & 0xFF) << 8) |
                              ((b2 & 0xFF) << 16) | ((b3 & 0xFF) << 24);
    }
    atomicMax(&g_smaxc, sa);
    const float denom = 2.0f * (maxz * (1.0f / 127.0f)) * (maxc * (1.0f / 127.0f));
    float v = (denom > 0.0f) ? g_cbnorm[k] / denom : 0.0f;
    g_cnint[k] = __float2int_rn(fminf(fmaxf(v, -2.0e9f), 2.0e9f));
}

// ---------------------------------------------------------------------------
// main fused kernel: int8 dp4a screen -> exact rescore -> quantized + loss.
// 512 threads, one token/thread, grid 256.
// ---------------------------------------------------------------------------
__global__ __launch_bounds__(512, 1)
void vq_kernel(const float* __restrict__ z,
               const float* __restrict__ cb,
               float* __restrict__ out_q,
               float* __restrict__ out_i,
               float* __restrict__ loss_ptr) {
    __shared__ int4   s_img[K_ * 4];    // 32KB int8 codebook image
    __shared__ int    s_cn[K_];         // 2KB cn_int
    __shared__ float  s_wsum[16];
    __shared__ bool   s_last;
    __shared__ double s_rd[256];

    const int tid  = threadIdx.x;
    const int wid  = tid >> 5;
    const int lane = tid & 31;

    // stage image + cn_int
    {
        const int4* src = reinterpret_cast<const int4*>(g_cbimg);
#pragma unroll
        for (int i = tid; i < K_ * 4; i += 512) s_img[i] = src[i];
        s_cn[tid] = g_cnint[tid];
    }

    const int n = blockIdx.x * 512 + tid;                 // token id
    const float* zc = z + ((size_t)(n >> 12) << 18) + (n & 4095);

    // z load (coalesced), canonical A, int8 pack (negated) + sum|z_hat|
    float zr[D_];
#pragma unroll
    for (int i = 0; i < D_; ++i) zr[i] = zc[(size_t)i << 12];
    float A = 0.0f;
#pragma unroll
    for (int i = 0; i < D_; ++i) A = fmaf(zr[i], zr[i], A);

    const float maxz = __uint_as_float(g_maxz_bits);
    const float inv_sz = (maxz > 0.0f) ? 127.0f / maxz : 0.0f;
    int zp[16];
    int sabs = 0;
#pragma unroll
    for (int j = 0; j < 16; ++j) {
        int b0 = min(127, max(-127, __float2int_rn(zr[4 * j + 0] * inv_sz)));
        int b1 = min(127, max(-127, __float2int_rn(zr[4 * j + 1] * inv_sz)));
        int b2 = min(127, max(-127, __float2int_rn(zr[4 * j + 2] * inv_sz)));
        int b3 = min(127, max(-127, __float2int_rn(zr[4 * j + 3] * inv_sz)));
        sabs += abs(b0) + abs(b1) + abs(b2) + abs(b3);
        zp[j] = ((-b0) & 0xFF) | (((-b1) & 0xFF) << 8) |
                (((-b2) & 0xFF) << 16) | (((-b3) & 0xFF) << 24);
    }

    // sound pruning margin (int score units of 2*s_z*s_c)
    const float maxc  = __uint_as_float(g_maxc_bits);
    const float denom = 2.0f * (maxz * (1.0f / 127.0f)) * (maxc * (1.0f / 127.0f));
    const float slack_f = (denom > 0.0f) ? 2.0e-4f / denom : 4.0e9f;
    const int   slack   = (slack_f < 1.0e9f) ? ((int)slack_f + 2) : (1 << 29);
    long long ml = (long long)sabs + (long long)g_smaxc + 120 + 2LL * (long long)slack;
    const int margin = (int)((ml < (long long)(1 << 29)) ? ml : (long long)(1 << 29));

    __syncthreads();

    // ---- integer screen: 16 dp4a per code, candidates vs running threshold ----
    int ck[CAP_];
    int cc  = 0;
    int thr = 0x7FFFFFFF;
#pragma unroll 2
    for (int k = 0; k < K_; ++k) {
        int4 c0 = s_img[4 * k + 0], c1 = s_img[4 * k + 1];
        int4 c2 = s_img[4 * k + 2], c3 = s_img[4 * k + 3];
        int a0 = s_cn[k], a1 = 0, a2 = 0, a3 = 0;
        a0 = __dp4a(zp[0],  c0.x, a0);  a1 = __dp4a(zp[1],  c0.y, a1);
        a2 = __dp4a(zp[2],  c0.z, a2);  a3 = __dp4a(zp[3],  c0.w, a3);
        a0 = __dp4a(zp[4],  c1.x, a0);  a1 = __dp4a(zp[5],  c1.y, a1);
        a2 = __dp4a(zp[6],  c1.z, a2);  a3 = __dp4a(zp[7],  c1.w, a3);
        a0 = __dp4a(zp[8],  c2.x, a0);  a1 = __dp4a(zp[9],  c2.y, a1);
        a2 = __dp4a(zp[10], c2.z, a2);  a3 = __dp4a(zp[11], c2.w, a3);
        a0 = __dp4a(zp[12], c3.x, a0);  a1 = __dp4a(zp[13], c3.y, a1);
        a2 = __dp4a(zp[14], c3.z, a2);  a3 = __dp4a(zp[15], c3.w, a3);
        int score = (a0 + a1) + (a2 + a3);      // = cn_int - idot
        if (score <= thr) { if (cc < CAP_) ck[cc] = k; ++cc; }
        thr = min(thr, score + margin);
    }

    // ---- exact fp32 rescore (bitwise round-0 arithmetic) ----
    int bestk;
    if (cc == 1) {
        bestk = ck[0];
    } else if (cc <= CAP_) {
        float bd = 3.402823466e38f;
        bestk = 0;
        for (int j = 0; j < cc; ++j) {          // ascending k -> first-index ties
            int k = ck[j];
            float dd = exact_dist(zr, A, cb, k);
            if (dd < bd) { bd = dd; bestk = k; }
        }
    } else {
        float bd = 3.402823466e38f;             // overflow fallback: full scan
        bestk = 0;
        for (int k = 0; k < K_; ++k) {
            float dd = exact_dist(zr, A, cb, k);
            if (dd < bd) { bd = dd; bestk = k; }
        }
    }

    if (out_i) out_i[n] = (float)bestk;

    // ---- fused quantized output (fl(z + fl(q - z))) + loss partial ----
    float acc = 0.0f;
    const float4* qr = reinterpret_cast<const float4*>(cb + (size_t)bestk * D_);
    float* oq = out_q ? out_q + ((size_t)(n >> 12) << 18) + (n & 4095) : nullptr;
#pragma unroll
    for (int j = 0; j < 16; ++j) {
        float4 qv = __ldg(qr + j);
        float d0 = __fsub_rn(qv.x, zr[4 * j + 0]);
        float d1 = __fsub_rn(qv.y, zr[4 * j + 1]);
        float d2 = __fsub_rn(qv.z, zr[4 * j + 2]);
        float d3 = __fsub_rn(qv.w, zr[4 * j + 3]);
        if (oq) {
            oq[(size_t)(4 * j + 0) << 12] = __fadd_rn(zr[4 * j + 0], d0);
            oq[(size_t)(4 * j + 1) << 12] = __fadd_rn(zr[4 * j + 1], d1);
            oq[(size_t)(4 * j + 2) << 12] = __fadd_rn(zr[4 * j + 2], d2);
            oq[(size_t)(4 * j + 3) << 12] = __fadd_rn(zr[4 * j + 3], d3);
        }
        acc = fmaf(d0, d0, acc);
        acc = fmaf(d1, d1, acc);
        acc = fmaf(d2, d2, acc);
        acc = fmaf(d3, d3, acc);
    }
#pragma unroll
    for (int o = 16; o > 0; o >>= 1) acc += __shfl_xor_sync(0xffffffffu, acc, o);
    if (lane == 0) s_wsum[wid] = acc;
    __syncthreads();
    if (tid == 0) {
        float s = 0.0f;
#pragma unroll
        for (int i = 0; i < 16; ++i) s += s_wsum[i];
        g_partial[blockIdx.x] = s;
        __threadfence();
        unsigned int ticket = atomicAdd(&g_count, 1u);
        s_last = (ticket == 255u);
    }
    __syncthreads();

    if (s_last) {
        double s = 0.0;
        if (tid < 256) s = (double)g_partial[tid];
        s_rd[tid & 255] = 0.0;
        __syncthreads();
        if (tid < 256) s_rd[tid] = s;
        __syncthreads();
        for (int st = 128; st > 0; st >>= 1) {
            if (tid < st) s_rd[tid] += s_rd[tid + st];
            __syncthreads();
        }
        if (tid == 0) {
            if (loss_ptr) {
                float cl = (float)(s_rd[0] / (double)NQ_);
                loss_ptr[0] = __fadd_rn(cl, __fmul_rn(0.25f, cl));
            }
            g_count = 0;   // reset for next graph replay
        }
    }
}

// ---------------------------------------------------------------------------
extern "C" void kernel_launch(void* const* d_in, const int* in_sizes, int n_in,
                              void* d_out, int out_size) {
    const float* z  = nullptr;
    const float* cb = nullptr;
    for (int i = 0; i < n_in; ++i) {
        if (in_sizes[i] == NQ_)          z  = (const float*)d_in[i];
        else if (in_sizes[i] == K_ * D_) cb = (const float*)d_in[i];
    }
    if (!z || !cb) return;

    float* out = (float*)d_out;
    float* loss_ptr = nullptr;
    float* q_ptr    = nullptr;
    float* i_ptr    = nullptr;

    if (out_size == 1 + NQ_ + N_) {
        loss_ptr = out; q_ptr = out + 1; i_ptr = out + 1 + NQ_;
    } else if (out_size == NQ_ + N_) {
        q_ptr = out; i_ptr = out + NQ_;
    } else if (out_size == NQ_) {
        q_ptr = out;
    } else if (out_size == N_) {
        i_ptr = out;
    } else if (out_size == 1) {
        loss_ptr = out;
    } else if (out_size > 1 + NQ_ + N_) {
        loss_ptr = out; q_ptr = out + 1; i_ptr = out + 1 + NQ_;
    }

    prep_z_kernel<<<512, 256>>>(z);
    prep_cb1_kernel<<<2, 256>>>(cb);
    prep_cb2_kernel<<<2, 256>>>(cb);
    vq_kernel<<<N_ / 512, 512>>>(z, cb, q_ptr, i_ptr, loss_ptr);
}

// round 7
// speedup vs baseline: 1.2275x; 1.2275x over previous
#include <cuda_runtime.h>
#include <cstdint>

// Problem constants (fixed by the reference)
#define B_ 32
#define D_ 64
#define T_ 4096
#define K_ 512
#define N_ (B_ * T_)        // 131072 tokens
#define NQ_ (B_ * D_ * T_)  // 8388608 quantized elements

// Scratch (device globals: no allocation allowed)
__device__ unsigned int g_maxz_bits;
__device__ unsigned int g_maxc_bits;
__device__ int          g_smaxc;
__device__ float        g_cbnorm[K_];
__device__ int          g_cnint[K_];
__device__ __align__(16) int g_cbimg[K_ * 16];
__device__ float        g_partial[256];
__device__ unsigned int g_count;

// ---------------------------------------------------------------------------
// Exact fp32 distance, STREAMING z from gmem (identical arithmetic to the
// proven round-0 formula: 4 stride-4 fmaf chains, canonical combine).
// ---------------------------------------------------------------------------
__device__ __forceinline__ float exact_dist_stream(const float* __restrict__ zc,
                                                   float A,
                                                   const float* __restrict__ cb,
                                                   int k) {
    const float4* cp = reinterpret_cast<const float4*>(cb + (size_t)k * D_);
    float s0 = 0.f, s1 = 0.f, s2 = 0.f, s3 = 0.f;
#pragma unroll
    for (int i = 0; i < 16; ++i) {
        float4 c = __ldg(cp + i);
        s0 = fmaf(zc[(size_t)(4 * i + 0) << 12], c.x, s0);
        s1 = fmaf(zc[(size_t)(4 * i + 1) << 12], c.y, s1);
        s2 = fmaf(zc[(size_t)(4 * i + 2) << 12], c.z, s2);
        s3 = fmaf(zc[(size_t)(4 * i + 3) << 12], c.w, s3);
    }
    float dot = __fadd_rn(__fadd_rn(s0, s1), __fadd_rn(s2, s3));
    float cn  = __ldg(&g_cbnorm[k]);
    return __fadd_rn(__fadd_rn(A, cn), -__fmul_rn(2.0f, dot));
}

// ---------------------------------------------------------------------------
// prep 0: global max |z|
// ---------------------------------------------------------------------------
__global__ void prep_z_kernel(const float* __restrict__ z) {
    const float4* z4 = reinterpret_cast<const float4*>(z);
    float m = 0.0f;
    for (int j = blockIdx.x * blockDim.x + threadIdx.x; j < NQ_ / 4;
         j += gridDim.x * blockDim.x) {
        float4 v = z4[j];
        m = fmaxf(m, fmaxf(fmaxf(fabsf(v.x), fabsf(v.y)),
                           fmaxf(fabsf(v.z), fabsf(v.w))));
    }
#pragma unroll
    for (int o = 16; o > 0; o >>= 1) m = fmaxf(m, __shfl_xor_sync(0xffffffffu, m, o));
    if ((threadIdx.x & 31) == 0) atomicMax(&g_maxz_bits, __float_as_uint(m));
}

// prep 1: exact norms (canonical fmaf order) + max |c|
__global__ void prep_cb1_kernel(const float* __restrict__ cb) {
    int k = blockIdx.x * blockDim.x + threadIdx.x;
    if (k < K_) {
        const float* r = cb + k * D_;
        float a = 0.0f, mx = 0.0f;
#pragma unroll
        for (int i = 0; i < D_; ++i) {
            a = fmaf(r[i], r[i], a);
            mx = fmaxf(mx, fabsf(r[i]));
        }
        g_cbnorm[k] = a;
        atomicMax(&g_maxc_bits, __float_as_uint(mx));
    }
}

// prep 2: int8 image, max sum|c_hat|, cn_int
__global__ void prep_cb2_kernel(const float* __restrict__ cb) {
    int k = blockIdx.x * blockDim.x + threadIdx.x;
    if (k >= K_) return;
    const float maxz = __uint_as_float(g_maxz_bits);
    const float maxc = __uint_as_float(g_maxc_bits);
    const float inv_sc = (maxc > 0.0f) ? 127.0f / maxc : 0.0f;
    const float* r = cb + k * D_;
    int sa = 0;
#pragma unroll
    for (int j = 0; j < 16; ++j) {
        int b0 = min(127, max(-127, __float2int_rn(r[4 * j + 0] * inv_sc)));
        int b1 = min(127, max(-127, __float2int_rn(r[4 * j + 1] * inv_sc)));
        int b2 = min(127, max(-127, __float2int_rn(r[4 * j + 2] * inv_sc)));
        int b3 = min(127, max(-127, __float2int_rn(r[4 * j + 3] * inv_sc)));
        sa += abs(b0) + abs(b1) + abs(b2) + abs(b3);
        g_cbimg[k * 16 + j] = (b0 & 0xFF) | ((b1 & 0xFF) << 8) |
                              ((b2 & 0xFF) << 16) | ((b3 & 0xFF) << 24);
    }
    atomicMax(&g_smaxc, sa);
    const float denom = 2.0f * (maxz * (1.0f / 127.0f)) * (maxc * (1.0f / 127.0f));
    float v = (denom > 0.0f) ? g_cbnorm[k] / denom : 0.0f;
    g_cnint[k] = __float2int_rn(fminf(fmaxf(v, -2.0e9f), 2.0e9f));
}

// ---------------------------------------------------------------------------
// fused VQ kernel: spill-free dp4a screen (bitmask candidates) -> streaming
// exact rescore -> quantized output + loss. 512 thd, 2 blocks/SM, grid 256.
// ---------------------------------------------------------------------------
#define SM_IMG   0                        // 512*16 int  = 32768 B
#define SM_CN    32768                    // 512 int     = 2048 B
#define SM_MASK  34816                    // 16*512 uint = 32768 B
#define SM_WSUM  67584                    // 16 float
#define SM_RD    67712                    // 256 double  = 2048 B (16B aligned)
#define SM_LAST  69760                    // 1 int
#define SM_TOT   69824

__global__ __launch_bounds__(512, 2)
void vq_kernel(const float* __restrict__ z,
               const float* __restrict__ cb,
               float* __restrict__ out_q,
               float* __restrict__ out_i,
               float* __restrict__ loss_ptr) {
    extern __shared__ char sm[];
    int4*     s_img  = reinterpret_cast<int4*>(sm + SM_IMG);
    int*      s_cn   = reinterpret_cast<int*>(sm + SM_CN);
    unsigned* s_mask = reinterpret_cast<unsigned*>(sm + SM_MASK);
    float*    s_wsum = reinterpret_cast<float*>(sm + SM_WSUM);
    double*   s_rd   = reinterpret_cast<double*>(sm + SM_RD);
    int*      s_last = reinterpret_cast<int*>(sm + SM_LAST);

    const int tid  = threadIdx.x;
    const int wid  = tid >> 5;
    const int lane = tid & 31;

    // ---- stage int8 image + cn_int ----
    {
        const int4* src = reinterpret_cast<const int4*>(g_cbimg);
#pragma unroll
        for (int i = tid; i < K_ * 4; i += 512) s_img[i] = src[i];
        s_cn[tid] = g_cnint[tid];
    }

    // ---- phase 1: stream z once -> A (canonical order), zp packed, sabs ----
    const int n = blockIdx.x * 512 + tid;
    const float* zc = z + ((size_t)(n >> 12) << 18) + (n & 4095);

    const float maxz = __uint_as_float(g_maxz_bits);
    const float inv_sz = (maxz > 0.0f) ? 127.0f / maxz : 0.0f;
    float A = 0.0f;
    int zp[16];
    int sabs = 0;
#pragma unroll
    for (int j = 0; j < 16; ++j) {
        float z0 = zc[(size_t)(4 * j + 0) << 12];
        float z1 = zc[(size_t)(4 * j + 1) << 12];
        float z2 = zc[(size_t)(4 * j + 2) << 12];
        float z3 = zc[(size_t)(4 * j + 3) << 12];
        A = fmaf(z0, z0, A);
        A = fmaf(z1, z1, A);
        A = fmaf(z2, z2, A);
        A = fmaf(z3, z3, A);
        int b0 = min(127, max(-127, __float2int_rn(z0 * inv_sz)));
        int b1 = min(127, max(-127, __float2int_rn(z1 * inv_sz)));
        int b2 = min(127, max(-127, __float2int_rn(z2 * inv_sz)));
        int b3 = min(127, max(-127, __float2int_rn(z3 * inv_sz)));
        sabs += abs(b0) + abs(b1) + abs(b2) + abs(b3);
        zp[j] = ((-b0) & 0xFF) | (((-b1) & 0xFF) << 8) |
                (((-b2) & 0xFF) << 16) | (((-b3) & 0xFF) << 24);
    }

    // sound margin (verbatim round-6 formula, proven rel_err = 0.0)
    const float maxc  = __uint_as_float(g_maxc_bits);
    const float denom = 2.0f * (maxz * (1.0f / 127.0f)) * (maxc * (1.0f / 127.0f));
    const float slack_f = (denom > 0.0f) ? 2.0e-4f / denom : 4.0e9f;
    const int   slack   = (slack_f < 1.0e9f) ? ((int)slack_f + 2) : (1 << 29);
    long long ml = (long long)sabs + (long long)g_smaxc + 120 + 2LL * (long long)slack;
    const int margin = (int)((ml < (long long)(1 << 29)) ? ml : (long long)(1 << 29));

    __syncthreads();

    // ---- phase 2: dp4a screen, candidates into shared bitmask ----
    int thr = 0x7FFFFFFF;
#pragma unroll 1
    for (int m = 0; m < 16; ++m) {
        unsigned bits = 0;
        const int4* cp = s_img + m * 128;
#pragma unroll 4
        for (int j = 0; j < 32; ++j) {
            int4 c0 = cp[4 * j + 0], c1 = cp[4 * j + 1];
            int4 c2 = cp[4 * j + 2], c3 = cp[4 * j + 3];
            int a0 = s_cn[m * 32 + j], a1 = 0, a2 = 0, a3 = 0;
            a0 = __dp4a(zp[0],  c0.x, a0);  a1 = __dp4a(zp[1],  c0.y, a1);
            a2 = __dp4a(zp[2],  c0.z, a2);  a3 = __dp4a(zp[3],  c0.w, a3);
            a0 = __dp4a(zp[4],  c1.x, a0);  a1 = __dp4a(zp[5],  c1.y, a1);
            a2 = __dp4a(zp[6],  c1.z, a2);  a3 = __dp4a(zp[7],  c1.w, a3);
            a0 = __dp4a(zp[8],  c2.x, a0);  a1 = __dp4a(zp[9],  c2.y, a1);
            a2 = __dp4a(zp[10], c2.z, a2);  a3 = __dp4a(zp[11], c2.w, a3);
            a0 = __dp4a(zp[12], c3.x, a0);  a1 = __dp4a(zp[13], c3.y, a1);
            a2 = __dp4a(zp[14], c3.z, a2);  a3 = __dp4a(zp[15], c3.w, a3);
            int score = (a0 + a1) + (a2 + a3);
            if (score <= thr) bits |= (1u << j);
            thr = min(thr, score + margin);
        }
        s_mask[m * 512 + tid] = bits;   // conflict-free: consecutive tid
    }

    // ---- phase 3: exact rescore of pushed candidates (streamed z) ----
    float bd = 3.402823466e38f;
    int bestk = 0;
#pragma unroll 1
    for (int m = 0; m < 16; ++m) {
        unsigned bits = s_mask[m * 512 + tid];
        while (bits) {
            int j = __ffs(bits) - 1;
            bits &= bits - 1;
            int k = m * 32 + j;
            float dd = exact_dist_stream(zc, A, cb, k);
            if (dd < bd) { bd = dd; bestk = k; }   // ascending k: first-min ties
        }
    }

    if (out_i) out_i[n] = (float)bestk;

    // ---- phase 4: quantized output (fl(z + fl(q-z))) + loss partial ----
    float acc = 0.0f;
    const float4* qr = reinterpret_cast<const float4*>(cb + (size_t)bestk * D_);
    float* oq = out_q ? out_q + ((size_t)(n >> 12) << 18) + (n & 4095) : nullptr;
#pragma unroll
    for (int j = 0; j < 16; ++j) {
        float4 qv = __ldg(qr + j);
        float zv0 = zc[(size_t)(4 * j + 0) << 12];
        float zv1 = zc[(size_t)(4 * j + 1) << 12];
        float zv2 = zc[(size_t)(4 * j + 2) << 12];
        float zv3 = zc[(size_t)(4 * j + 3) << 12];
        float d0 = __fsub_rn(qv.x, zv0);
        float d1 = __fsub_rn(qv.y, zv1);
        float d2 = __fsub_rn(qv.z, zv2);
        float d3 = __fsub_rn(qv.w, zv3);
        if (oq) {
            oq[(size_t)(4 * j + 0) << 12] = __fadd_rn(zv0, d0);
            oq[(size_t)(4 * j + 1) << 12] = __fadd_rn(zv1, d1);
            oq[(size_t)(4 * j + 2) << 12] = __fadd_rn(zv2, d2);
            oq[(size_t)(4 * j + 3) << 12] = __fadd_rn(zv3, d3);
        }
        acc = fmaf(d0, d0, acc);
        acc = fmaf(d1, d1, acc);
        acc = fmaf(d2, d2, acc);
        acc = fmaf(d3, d3, acc);
    }
#pragma unroll
    for (int o = 16; o > 0; o >>= 1) acc += __shfl_xor_sync(0xffffffffu, acc, o);
    if (lane == 0) s_wsum[wid] = acc;
    __syncthreads();
    if (tid == 0) {
        float s = 0.0f;
#pragma unroll
        for (int i = 0; i < 16; ++i) s += s_wsum[i];
        g_partial[blockIdx.x] = s;
        __threadfence();
        unsigned int ticket = atomicAdd(&g_count, 1u);
        s_last[0] = (ticket == 255u) ? 1 : 0;
    }
    __syncthreads();

    // ---- last block: deterministic finalize ----
    if (s_last[0]) {
        if (tid < 256) s_rd[tid] = (double)g_partial[tid];
        __syncthreads();
        for (int st = 128; st > 0; st >>= 1) {
            if (tid < st) s_rd[tid] += s_rd[tid + st];
            __syncthreads();
        }
        if (tid == 0) {
            if (loss_ptr) {
                float cl = (float)(s_rd[0] / (double)NQ_);
                loss_ptr[0] = __fadd_rn(cl, __fmul_rn(0.25f, cl));
            }
            g_count = 0;   // reset for next graph replay
        }
    }
}

// ---------------------------------------------------------------------------
extern "C" void kernel_launch(void* const* d_in, const int* in_sizes, int n_in,
                              void* d_out, int out_size) {
    const float* z  = nullptr;
    const float* cb = nullptr;
    for (int i = 0; i < n_in; ++i) {
        if (in_sizes[i] == NQ_)          z  = (const float*)d_in[i];
        else if (in_sizes[i] == K_ * D_) cb = (const float*)d_in[i];
    }
    if (!z || !cb) return;

    float* out = (float*)d_out;
    float* loss_ptr = nullptr;
    float* q_ptr    = nullptr;
    float* i_ptr    = nullptr;

    if (out_size == 1 + NQ_ + N_) {
        loss_ptr = out; q_ptr = out + 1; i_ptr = out + 1 + NQ_;
    } else if (out_size == NQ_ + N_) {
        q_ptr = out; i_ptr = out + NQ_;
    } else if (out_size == NQ_) {
        q_ptr = out;
    } else if (out_size == N_) {
        i_ptr = out;
    } else if (out_size == 1) {
        loss_ptr = out;
    } else if (out_size > 1 + NQ_ + N_) {
        loss_ptr = out; q_ptr = out + 1; i_ptr = out + 1 + NQ_;
    }

    static bool attr_done = false;
    if (!attr_done) {
        cudaFuncSetAttribute(vq_kernel,
                             cudaFuncAttributeMaxDynamicSharedMemorySize,
                             SM_TOT);
        attr_done = true;
    }

    prep_z_kernel<<<512, 256>>>(z);
    prep_cb1_kernel<<<2, 256>>>(cb);
    prep_cb2_kernel<<<2, 256>>>(cb);
    vq_kernel<<<N_ / 512, 512, SM_TOT>>>(z, cb, q_ptr, i_ptr, loss_ptr);
}

// round 8
// speedup vs baseline: 1.9907x; 1.6217x over previous
#include <cuda_runtime.h>
#include <cstdint>

// Problem constants (fixed by the reference)
#define B_ 32
#define D_ 64
#define T_ 4096
#define K_ 512
#define N_ (B_ * T_)        // 131072 tokens
#define NQ_ (B_ * D_ * T_)  // 8388608 quantized elements

// Scratch (device globals: no allocation allowed)
__device__ unsigned int g_maxz_bits;
__device__ unsigned int g_maxc_bits;
__device__ int          g_smaxc;
__device__ float        g_cbnorm[K_];
__device__ int          g_cnint[K_];
__device__ __align__(16) int g_cbimg[K_ * 16];
__device__ float        g_partial[256];
__device__ unsigned int g_count;

// ---------------------------------------------------------------------------
// prep 0: global max |z|
// ---------------------------------------------------------------------------
__global__ void prep_z_kernel(const float* __restrict__ z) {
    const float4* z4 = reinterpret_cast<const float4*>(z);
    float m = 0.0f;
    for (int j = blockIdx.x * blockDim.x + threadIdx.x; j < NQ_ / 4;
         j += gridDim.x * blockDim.x) {
        float4 v = z4[j];
        m = fmaxf(m, fmaxf(fmaxf(fabsf(v.x), fabsf(v.y)),
                           fmaxf(fabsf(v.z), fabsf(v.w))));
    }
#pragma unroll
    for (int o = 16; o > 0; o >>= 1) m = fmaxf(m, __shfl_xor_sync(0xffffffffu, m, o));
    if ((threadIdx.x & 31) == 0) atomicMax(&g_maxz_bits, __float_as_uint(m));
}

// prep 1: exact norms (canonical fmaf order, proven rel_err = 0.0) + max |c|
__global__ void prep_cb1_kernel(const float* __restrict__ cb) {
    int k = blockIdx.x * blockDim.x + threadIdx.x;
    if (k < K_) {
        const float* r = cb + k * D_;
        float a = 0.0f, mx = 0.0f;
#pragma unroll
        for (int i = 0; i < D_; ++i) {
            a = fmaf(r[i], r[i], a);
            mx = fmaxf(mx, fabsf(r[i]));
        }
        g_cbnorm[k] = a;
        atomicMax(&g_maxc_bits, __float_as_uint(mx));
    }
}

// prep 2: int8 image, max sum|c_hat|, cn_int
__global__ void prep_cb2_kernel(const float* __restrict__ cb) {
    int k = blockIdx.x * blockDim.x + threadIdx.x;
    if (k >= K_) return;
    const float maxz = __uint_as_float(g_maxz_bits);
    const float maxc = __uint_as_float(g_maxc_bits);
    const float inv_sc = (maxc > 0.0f) ? 127.0f / maxc : 0.0f;
    const float* r = cb + k * D_;
    int sa = 0;
#pragma unroll
    for (int j = 0; j < 16; ++j) {
        int b0 = min(127, max(-127, __float2int_rn(r[4 * j + 0] * inv_sc)));
        int b1 = min(127, max(-127, __float2int_rn(r[4 * j + 1] * inv_sc)));
        int b2 = min(127, max(-127, __float2int_rn(r[4 * j + 2] * inv_sc)));
        int b3 = min(127, max(-127, __float2int_rn(r[4 * j + 3] * inv_sc)));
        sa += abs(b0) + abs(b1) + abs(b2) + abs(b3);
        g_cbimg[k * 16 + j] = (b0 & 0xFF) | ((b1 & 0xFF) << 8) |
                              ((b2 & 0xFF) << 16) | ((b3 & 0xFF) << 24);
    }
    atomicMax(&g_smaxc, sa);
    const float denom = 2.0f * (maxz * (1.0f / 127.0f)) * (maxc * (1.0f / 127.0f));
    float v = (denom > 0.0f) ? g_cbnorm[k] / denom : 0.0f;
    g_cnint[k] = __float2int_rn(fminf(fmaxf(v, -2.0e9f), 2.0e9f));
}

// ---------------------------------------------------------------------------
// Exact fp32 distance from PADDED smem codebook (row stride 17 float4 units).
// Arithmetic bit-identical to the proven round-0 formula.
// ---------------------------------------------------------------------------
__device__ __forceinline__ float exact_dist_sm(const float* zr, float A,
                                               const float4* __restrict__ cbf,
                                               const float* __restrict__ cnf,
                                               int k) {
    const float4* cp = cbf + k * 17;
    float s0 = 0.f, s1 = 0.f, s2 = 0.f, s3 = 0.f;
#pragma unroll
    for (int i = 0; i < 16; ++i) {
        float4 c = cp[i];
        s0 = fmaf(zr[4 * i + 0], c.x, s0);
        s1 = fmaf(zr[4 * i + 1], c.y, s1);
        s2 = fmaf(zr[4 * i + 2], c.z, s2);
        s3 = fmaf(zr[4 * i + 3], c.w, s3);
    }
    float dot = __fadd_rn(__fadd_rn(s0, s1), __fadd_rn(s2, s3));
    return __fadd_rn(__fadd_rn(A, cnf[k]), -__fmul_rn(2.0f, dot));
}

// ---------------------------------------------------------------------------
// fused VQ kernel. 512 thd, 1 block/SM (smem ~206KB), grid 256.
// smem layout (16B-aligned offsets):
// ---------------------------------------------------------------------------
#define SM_IMG   0                            // 512*16 int        = 32768
#define SM_CN    32768                        // 512 int (cn_int)  =  2048
#define SM_CNF   34816                        // 512 float (cn fp) =  2048
#define SM_CBF   36864                        // 512*17 float4     = 139264
#define SM_MASK  176128                       // 16*512 uint       = 32768
#define SM_WSUM  208896                       // 16 float          =    64
#define SM_RD    208960                       // 256 double        =  2048
#define SM_LAST  211008                       // int (+pad)        =    16
#define SM_TOT   211024

__global__ __launch_bounds__(512, 1)
void vq_kernel(const float* __restrict__ z,
               const float* __restrict__ cb,
               float* __restrict__ out_q,
               float* __restrict__ out_i,
               float* __restrict__ loss_ptr) {
    extern __shared__ char sm[];
    int4*     s_img  = reinterpret_cast<int4*>(sm + SM_IMG);
    int*      s_cn   = reinterpret_cast<int*>(sm + SM_CN);
    float*    s_cnf  = reinterpret_cast<float*>(sm + SM_CNF);
    float4*   s_cbf  = reinterpret_cast<float4*>(sm + SM_CBF);
    unsigned* s_mask = reinterpret_cast<unsigned*>(sm + SM_MASK);
    float*    s_wsum = reinterpret_cast<float*>(sm + SM_WSUM);
    double*   s_rd   = reinterpret_cast<double*>(sm + SM_RD);
    int*      s_last = reinterpret_cast<int*>(sm + SM_LAST);

    const int tid  = threadIdx.x;
    const int wid  = tid >> 5;
    const int lane = tid & 31;

    // ---- stage: int8 image, cn_int, fp32 cn, padded fp32 codebook ----
    {
        const int4* src = reinterpret_cast<const int4*>(g_cbimg);
#pragma unroll
        for (int i = tid; i < K_ * 4; i += 512) s_img[i] = src[i];
        s_cn[tid]  = g_cnint[tid];
        s_cnf[tid] = g_cbnorm[tid];
        const float4* cb4 = reinterpret_cast<const float4*>(cb);
#pragma unroll
        for (int i = tid; i < K_ * 16; i += 512)
            s_cbf[(i >> 4) * 17 + (i & 15)] = cb4[i];
    }

    // ---- phase 1: z into registers (once), canonical A, int8 pack, sabs ----
    const int n = blockIdx.x * 512 + tid;
    const size_t zoff = ((size_t)(n >> 12) << 18) + (size_t)(n & 4095);
    const float* zc = z + zoff;

    float zr[D_];
#pragma unroll
    for (int i = 0; i < D_; ++i) zr[i] = zc[(size_t)i << 12];
    float A = 0.0f;
#pragma unroll
    for (int i = 0; i < D_; ++i) A = fmaf(zr[i], zr[i], A);

    const float maxz = __uint_as_float(g_maxz_bits);
    const float inv_sz = (maxz > 0.0f) ? 127.0f / maxz : 0.0f;
    int zp[16];
    int sabs = 0;
#pragma unroll
    for (int j = 0; j < 16; ++j) {
        int b0 = min(127, max(-127, __float2int_rn(zr[4 * j + 0] * inv_sz)));
        int b1 = min(127, max(-127, __float2int_rn(zr[4 * j + 1] * inv_sz)));
        int b2 = min(127, max(-127, __float2int_rn(zr[4 * j + 2] * inv_sz)));
        int b3 = min(127, max(-127, __float2int_rn(zr[4 * j + 3] * inv_sz)));
        sabs += abs(b0) + abs(b1) + abs(b2) + abs(b3);
        zp[j] = ((-b0) & 0xFF) | (((-b1) & 0xFF) << 8) |
                (((-b2) & 0xFF) << 16) | (((-b3) & 0xFF) << 24);
    }

    // sound margin (verbatim round-7 formula, proven rel_err = 0.0)
    const float maxc  = __uint_as_float(g_maxc_bits);
    const float denom = 2.0f * (maxz * (1.0f / 127.0f)) * (maxc * (1.0f / 127.0f));
    const float slack_f = (denom > 0.0f) ? 2.0e-4f / denom : 4.0e9f;
    const int   slack   = (slack_f < 1.0e9f) ? ((int)slack_f + 2) : (1 << 29);
    long long ml = (long long)sabs + (long long)g_smaxc + 120 + 2LL * (long long)slack;
    const int margin = (int)((ml < (long long)(1 << 29)) ? ml : (long long)(1 << 29));

    __syncthreads();

    // ---- phase 2: dp4a screen -> candidate bitmask in shared ----
    int thr = 0x7FFFFFFF;
#pragma unroll 1
    for (int m = 0; m < 16; ++m) {
        unsigned bits = 0;
        const int4* cp = s_img + m * 128;
#pragma unroll 4
        for (int j = 0; j < 32; ++j) {
            int4 c0 = cp[4 * j + 0], c1 = cp[4 * j + 1];
            int4 c2 = cp[4 * j + 2], c3 = cp[4 * j + 3];
            int a0 = s_cn[m * 32 + j], a1 = 0, a2 = 0, a3 = 0;
            a0 = __dp4a(zp[0],  c0.x, a0);  a1 = __dp4a(zp[1],  c0.y, a1);
            a2 = __dp4a(zp[2],  c0.z, a2);  a3 = __dp4a(zp[3],  c0.w, a3);
            a0 = __dp4a(zp[4],  c1.x, a0);  a1 = __dp4a(zp[5],  c1.y, a1);
            a2 = __dp4a(zp[6],  c1.z, a2);  a3 = __dp4a(zp[7],  c1.w, a3);
            a0 = __dp4a(zp[8],  c2.x, a0);  a1 = __dp4a(zp[9],  c2.y, a1);
            a2 = __dp4a(zp[10], c2.z, a2);  a3 = __dp4a(zp[11], c2.w, a3);
            a0 = __dp4a(zp[12], c3.x, a0);  a1 = __dp4a(zp[13], c3.y, a1);
            a2 = __dp4a(zp[14], c3.z, a2);  a3 = __dp4a(zp[15], c3.w, a3);
            int score = (a0 + a1) + (a2 + a3);
            if (score <= thr) bits |= (1u << j);
            thr = min(thr, score + margin);
        }
        s_mask[m * 512 + tid] = bits;
    }

    // ---- phase 3: exact rescore from padded smem codebook ----
    float bd = 3.402823466e38f;
    int bestk = 0;
#pragma unroll 1
    for (int m = 0; m < 16; ++m) {
        unsigned bits = s_mask[m * 512 + tid];
        while (bits) {
            int j = __ffs(bits) - 1;
            bits &= bits - 1;
            int k = m * 32 + j;
            float dd = exact_dist_sm(zr, A, s_cbf, s_cnf, k);
            if (dd < bd) { bd = dd; bestk = k; }   // ascending k: first-min ties
        }
    }

    if (out_i) out_i[n] = (float)bestk;

    // ---- phase 4: quantized output (fl(z + fl(q-z))) + loss partial ----
    float acc = 0.0f;
    const float4* qr = s_cbf + bestk * 17;
    float* oq = out_q ? out_q + zoff : nullptr;
#pragma unroll
    for (int j = 0; j < 16; ++j) {
        float4 qv = qr[j];
        float d0 = __fsub_rn(qv.x, zr[4 * j + 0]);
        float d1 = __fsub_rn(qv.y, zr[4 * j + 1]);
        float d2 = __fsub_rn(qv.z, zr[4 * j + 2]);
        float d3 = __fsub_rn(qv.w, zr[4 * j + 3]);
        if (oq) {
            oq[(size_t)(4 * j + 0) << 12] = __fadd_rn(zr[4 * j + 0], d0);
            oq[(size_t)(4 * j + 1) << 12] = __fadd_rn(zr[4 * j + 1], d1);
            oq[(size_t)(4 * j + 2) << 12] = __fadd_rn(zr[4 * j + 2], d2);
            oq[(size_t)(4 * j + 3) << 12] = __fadd_rn(zr[4 * j + 3], d3);
        }
        acc = fmaf(d0, d0, acc);
        acc = fmaf(d1, d1, acc);
        acc = fmaf(d2, d2, acc);
        acc = fmaf(d3, d3, acc);
    }
#pragma unroll
    for (int o = 16; o > 0; o >>= 1) acc += __shfl_xor_sync(0xffffffffu, acc, o);
    if (lane == 0) s_wsum[wid] = acc;
    __syncthreads();
    if (tid == 0) {
        float s = 0.0f;
#pragma unroll
        for (int i = 0; i < 16; ++i) s += s_wsum[i];
        g_partial[blockIdx.x] = s;
        __threadfence();
        unsigned int ticket = atomicAdd(&g_count, 1u);
        s_last[0] = (ticket == 255u) ? 1 : 0;
    }
    __syncthreads();

    // ---- last block: deterministic finalize ----
    if (s_last[0]) {
        if (tid < 256) s_rd[tid] = (double)g_partial[tid];
        __syncthreads();
        for (int st = 128; st > 0; st >>= 1) {
            if (tid < st) s_rd[tid] += s_rd[tid + st];
            __syncthreads();
        }
        if (tid == 0) {
            if (loss_ptr) {
                float cl = (float)(s_rd[0] / (double)NQ_);
                loss_ptr[0] = __fadd_rn(cl, __fmul_rn(0.25f, cl));
            }
            g_count = 0;   // reset for next graph replay
        }
    }
}

// ---------------------------------------------------------------------------
extern "C" void kernel_launch(void* const* d_in, const int* in_sizes, int n_in,
                              void* d_out, int out_size) {
    const float* z  = nullptr;
    const float* cb = nullptr;
    for (int i = 0; i < n_in; ++i) {
        if (in_sizes[i] == NQ_)          z  = (const float*)d_in[i];
        else if (in_sizes[i] == K_ * D_) cb = (const float*)d_in[i];
    }
    if (!z || !cb) return;

    float* out = (float*)d_out;
    float* loss_ptr = nullptr;
    float* q_ptr    = nullptr;
    float* i_ptr    = nullptr;

    if (out_size == 1 + NQ_ + N_) {
        loss_ptr = out; q_ptr = out + 1; i_ptr = out + 1 + NQ_;
    } else if (out_size == NQ_ + N_) {
        q_ptr = out; i_ptr = out + NQ_;
    } else if (out_size == NQ_) {
        q_ptr = out;
    } else if (out_size == N_) {
        i_ptr = out;
    } else if (out_size == 1) {
        loss_ptr = out;
    } else if (out_size > 1 + NQ_ + N_) {
        loss_ptr = out; q_ptr = out + 1; i_ptr = out + 1 + NQ_;
    }

    static bool attr_done = false;
    if (!attr_done) {
        cudaFuncSetAttribute(vq_kernel,
                             cudaFuncAttributeMaxDynamicSharedMemorySize,
                             SM_TOT);
        attr_done = true;
    }

    prep_z_kernel<<<512, 256>>>(z);
    prep_cb1_kernel<<<2, 256>>>(cb);
    prep_cb2_kernel<<<2, 256>>>(cb);
    vq_kernel<<<N_ / 512, 512, SM_TOT>>>(z, cb, q_ptr, i_ptr, loss_ptr);
}

// round 9
// speedup vs baseline: 2.0356x; 1.0226x over previous
#include <cuda_runtime.h>
#include <cstdint>

// Problem constants (fixed by the reference)
#define B_ 32
#define D_ 64
#define T_ 4096
#define K_ 512
#define N_ (B_ * T_)        // 131072 tokens
#define NQ_ (B_ * D_ * T_)  // 8388608 quantized elements

// Scratch (device globals: no allocation allowed)
__device__ unsigned int g_maxz_bits;
__device__ unsigned int g_maxc_bits;
__device__ float        g_cbnorm[K_];
__device__ int2         g_cnsc[K_];            // (cn_int, sum|c_hat|)
__device__ __align__(16) int g_cbimg[K_ * 16];
__device__ float        g_partial[256];
__device__ unsigned int g_count;

// ---------------------------------------------------------------------------
// prep 0: global max |z|
// ---------------------------------------------------------------------------
__global__ void prep_z_kernel(const float* __restrict__ z) {
    const float4* z4 = reinterpret_cast<const float4*>(z);
    float m = 0.0f;
    for (int j = blockIdx.x * blockDim.x + threadIdx.x; j < NQ_ / 4;
         j += gridDim.x * blockDim.x) {
        float4 v = z4[j];
        m = fmaxf(m, fmaxf(fmaxf(fabsf(v.x), fabsf(v.y)),
                           fmaxf(fabsf(v.z), fabsf(v.w))));
    }
#pragma unroll
    for (int o = 16; o > 0; o >>= 1) m = fmaxf(m, __shfl_xor_sync(0xffffffffu, m, o));
    if ((threadIdx.x & 31) == 0) atomicMax(&g_maxz_bits, __float_as_uint(m));
}

// prep 1: exact norms (canonical fmaf order, proven rel_err = 0.0) + max |c|
__global__ void prep_cb1_kernel(const float* __restrict__ cb) {
    int k = blockIdx.x * blockDim.x + threadIdx.x;
    if (k < K_) {
        const float* r = cb + k * D_;
        float a = 0.0f, mx = 0.0f;
#pragma unroll
        for (int i = 0; i < D_; ++i) {
            a = fmaf(r[i], r[i], a);
            mx = fmaxf(mx, fabsf(r[i]));
        }
        g_cbnorm[k] = a;
        atomicMax(&g_maxc_bits, __float_as_uint(mx));
    }
}

// prep 2: int8 image, per-code (cn_int, sum|c_hat|)
__global__ void prep_cb2_kernel(const float* __restrict__ cb) {
    int k = blockIdx.x * blockDim.x + threadIdx.x;
    if (k >= K_) return;
    const float maxz = __uint_as_float(g_maxz_bits);
    const float maxc = __uint_as_float(g_maxc_bits);
    const float inv_sc = (maxc > 0.0f) ? 127.0f / maxc : 0.0f;
    const float* r = cb + k * D_;
    int sa = 0;
#pragma unroll
    for (int j = 0; j < 16; ++j) {
        int b0 = min(127, max(-127, __float2int_rn(r[4 * j + 0] * inv_sc)));
        int b1 = min(127, max(-127, __float2int_rn(r[4 * j + 1] * inv_sc)));
        int b2 = min(127, max(-127, __float2int_rn(r[4 * j + 2] * inv_sc)));
        int b3 = min(127, max(-127, __float2int_rn(r[4 * j + 3] * inv_sc)));
        sa += abs(b0) + abs(b1) + abs(b2) + abs(b3);
        g_cbimg[k * 16 + j] = (b0 & 0xFF) | ((b1 & 0xFF) << 8) |
                              ((b2 & 0xFF) << 16) | ((b3 & 0xFF) << 24);
    }
    const float denom = 2.0f * (maxz * (1.0f / 127.0f)) * (maxc * (1.0f / 127.0f));
    float v = (denom > 0.0f) ? g_cbnorm[k] / denom : 0.0f;
    int cni = __float2int_rn(fminf(fmaxf(v, -2.0e9f), 2.0e9f));
    g_cnsc[k] = make_int2(cni, sa);
}

// ---------------------------------------------------------------------------
// Exact fp32 distance from PADDED smem codebook (row stride 17 float4 units).
// Bit-identical to the proven round-0 formula.
// ---------------------------------------------------------------------------
__device__ __forceinline__ float exact_dist_sm(const float* zr, float A,
                                               const float4* __restrict__ cbf,
                                               const float* __restrict__ cnf,
                                               int k) {
    const float4* cp = cbf + k * 17;
    float s0 = 0.f, s1 = 0.f, s2 = 0.f, s3 = 0.f;
#pragma unroll
    for (int i = 0; i < 16; ++i) {
        float4 c = cp[i];
        s0 = fmaf(zr[4 * i + 0], c.x, s0);
        s1 = fmaf(zr[4 * i + 1], c.y, s1);
        s2 = fmaf(zr[4 * i + 2], c.z, s2);
        s3 = fmaf(zr[4 * i + 3], c.w, s3);
    }
    float dot = __fadd_rn(__fadd_rn(s0, s1), __fadd_rn(s2, s3));
    return __fadd_rn(__fadd_rn(A, cnf[k]), -__fmul_rn(2.0f, dot));
}

// ---------------------------------------------------------------------------
// fused VQ kernel. 512 thd, 1 block/SM, grid 256.
// ---------------------------------------------------------------------------
#define SM_IMG   0                            // 2048 int4        =  32768
#define SM_CNSC  32768                        // 512 int2         =   4096
#define SM_CNF   36864                        // 512 float        =   2048
#define SM_CBF   38912                        // 512*17 float4    = 139264
#define SM_MASK  178176                       // 16*512 uint      =  32768
#define SM_WSUM  210944                       // 16 float         =     64
#define SM_RD    211008                       // 256 double       =   2048
#define SM_LAST  213056                       // int (+pad)       =     16
#define SM_TOT   213072

__global__ __launch_bounds__(512, 1)
void vq_kernel(const float* __restrict__ z,
               const float* __restrict__ cb,
               float* __restrict__ out_q,
               float* __restrict__ out_i,
               float* __restrict__ loss_ptr) {
    extern __shared__ char sm[];
    int4*     s_img  = reinterpret_cast<int4*>(sm + SM_IMG);
    int2*     s_cnsc = reinterpret_cast<int2*>(sm + SM_CNSC);
    float*    s_cnf  = reinterpret_cast<float*>(sm + SM_CNF);
    float4*   s_cbf  = reinterpret_cast<float4*>(sm + SM_CBF);
    unsigned* s_mask = reinterpret_cast<unsigned*>(sm + SM_MASK);
    float*    s_wsum = reinterpret_cast<float*>(sm + SM_WSUM);
    double*   s_rd   = reinterpret_cast<double*>(sm + SM_RD);
    int*      s_last = reinterpret_cast<int*>(sm + SM_LAST);

    const int tid  = threadIdx.x;
    const int wid  = tid >> 5;
    const int lane = tid & 31;

    // ---- stage: int8 image, (cn_int,sc), fp32 cn, padded fp32 codebook ----
    {
        const int4* src = reinterpret_cast<const int4*>(g_cbimg);
#pragma unroll
        for (int i = tid; i < K_ * 4; i += 512) s_img[i] = src[i];
        s_cnsc[tid] = g_cnsc[tid];
        s_cnf[tid]  = g_cbnorm[tid];
        const float4* cb4 = reinterpret_cast<const float4*>(cb);
#pragma unroll
        for (int i = tid; i < K_ * 16; i += 512)
            s_cbf[(i >> 4) * 17 + (i & 15)] = cb4[i];
    }

    // ---- phase 1: stream z (low register footprint): A canonical, zp, sabs ----
    const int n = blockIdx.x * 512 + tid;
    const size_t zoff = ((size_t)(n >> 12) << 18) + (size_t)(n & 4095);
    const float* zc = z + zoff;

    const float maxz = __uint_as_float(g_maxz_bits);
    const float inv_sz = (maxz > 0.0f) ? 127.0f / maxz : 0.0f;
    float A = 0.0f;
    int zp[16];
    int sabs = 0;
#pragma unroll
    for (int j = 0; j < 16; ++j) {
        float z0 = zc[(size_t)(4 * j + 0) << 12];
        float z1 = zc[(size_t)(4 * j + 1) << 12];
        float z2 = zc[(size_t)(4 * j + 2) << 12];
        float z3 = zc[(size_t)(4 * j + 3) << 12];
        A = fmaf(z0, z0, A);            // canonical i = 0..63 order
        A = fmaf(z1, z1, A);
        A = fmaf(z2, z2, A);
        A = fmaf(z3, z3, A);
        int b0 = min(127, max(-127, __float2int_rn(z0 * inv_sz)));
        int b1 = min(127, max(-127, __float2int_rn(z1 * inv_sz)));
        int b2 = min(127, max(-127, __float2int_rn(z2 * inv_sz)));
        int b3 = min(127, max(-127, __float2int_rn(z3 * inv_sz)));
        sabs += abs(b0) + abs(b1) + abs(b2) + abs(b3);
        zp[j] = ((-b0) & 0xFF) | (((-b1) & 0xFF) << 8) |
                (((-b2) & 0xFF) << 16) | (((-b3) & 0xFF) << 24);
    }

    // sound per-code margin, doubled score units:
    // candidate j iff 2*sig_j - sc_j <= min_k(2*sig_k + sc_k) + M
    const float maxc  = __uint_as_float(g_maxc_bits);
    const float denom = 2.0f * (maxz * (1.0f / 127.0f)) * (maxc * (1.0f / 127.0f));
    const float slack_f = (denom > 0.0f) ? 2.0e-4f / denom : 4.0e9f;
    const int   slack   = (slack_f < 1.0e9f) ? ((int)slack_f + 2) : (1 << 27);
    long long ml = 2LL * (long long)sabs + 4LL * (long long)slack + 240;
    const int M = (int)((ml < (long long)(1 << 29)) ? ml : (long long)(1 << 29));

    __syncthreads();

    // ---- phase 2: dp4a screen -> candidate bitmask in shared ----
    int thrM = 0x7FFFFFFF;
#pragma unroll 1
    for (int m = 0; m < 16; ++m) {
        unsigned bits = 0;
        const int4* cp = s_img + m * 128;
#pragma unroll 4
        for (int j = 0; j < 32; ++j) {
            int4 c0 = cp[4 * j + 0], c1 = cp[4 * j + 1];
            int4 c2 = cp[4 * j + 2], c3 = cp[4 * j + 3];
            int2 cs = s_cnsc[m * 32 + j];
            int a0 = cs.x, a1 = 0, a2 = 0, a3 = 0;
            a0 = __dp4a(zp[0],  c0.x, a0);  a1 = __dp4a(zp[1],  c0.y, a1);
            a2 = __dp4a(zp[2],  c0.z, a2);  a3 = __dp4a(zp[3],  c0.w, a3);
            a0 = __dp4a(zp[4],  c1.x, a0);  a1 = __dp4a(zp[5],  c1.y, a1);
            a2 = __dp4a(zp[6],  c1.z, a2);  a3 = __dp4a(zp[7],  c1.w, a3);
            a0 = __dp4a(zp[8],  c2.x, a0);  a1 = __dp4a(zp[9],  c2.y, a1);
            a2 = __dp4a(zp[10], c2.z, a2);  a3 = __dp4a(zp[11], c2.w, a3);
            a0 = __dp4a(zp[12], c3.x, a0);  a1 = __dp4a(zp[13], c3.y, a1);
            a2 = __dp4a(zp[14], c3.z, a2);  a3 = __dp4a(zp[15], c3.w, a3);
            int sig2 = 2 * ((a0 + a1) + (a2 + a3));
            int lo = sig2 - cs.y;
            int hi = sig2 + cs.y;
            if (lo <= thrM) bits |= (1u << j);
            thrM = min(thrM, hi + M);
        }
        s_mask[m * 512 + tid] = bits;
    }

    // ---- phase 3: load zr (registers now free), exact rescore from smem ----
    float zr[D_];
#pragma unroll
    for (int i = 0; i < D_; ++i) zr[i] = zc[(size_t)i << 12];

    float bd = 3.402823466e38f;
    int bestk = 0;
#pragma unroll 1
    for (int m = 0; m < 16; ++m) {
        unsigned bits = s_mask[m * 512 + tid];
        while (bits) {
            int j = __ffs(bits) - 1;
            bits &= bits - 1;
            int k = m * 32 + j;
            float dd = exact_dist_sm(zr, A, s_cbf, s_cnf, k);
            if (dd < bd) { bd = dd; bestk = k; }   // ascending k: first-min ties
        }
    }

    if (out_i) out_i[n] = (float)bestk;

    // ---- phase 4: quantized output (fl(z + fl(q-z))) + loss partial ----
    float acc = 0.0f;
    const float4* qr = s_cbf + bestk * 17;
    float* oq = out_q ? out_q + zoff : nullptr;
#pragma unroll
    for (int j = 0; j < 16; ++j) {
        float4 qv = qr[j];
        float d0 = __fsub_rn(qv.x, zr[4 * j + 0]);
        float d1 = __fsub_rn(qv.y, zr[4 * j + 1]);
        float d2 = __fsub_rn(qv.z, zr[4 * j + 2]);
        float d3 = __fsub_rn(qv.w, zr[4 * j + 3]);
        if (oq) {
            oq[(size_t)(4 * j + 0) << 12] = __fadd_rn(zr[4 * j + 0], d0);
            oq[(size_t)(4 * j + 1) << 12] = __fadd_rn(zr[4 * j + 1], d1);
            oq[(size_t)(4 * j + 2) << 12] = __fadd_rn(zr[4 * j + 2], d2);
            oq[(size_t)(4 * j + 3) << 12] = __fadd_rn(zr[4 * j + 3], d3);
        }
        acc = fmaf(d0, d0, acc);
        acc = fmaf(d1, d1, acc);
        acc = fmaf(d2, d2, acc);
        acc = fmaf(d3, d3, acc);
    }
#pragma unroll
    for (int o = 16; o > 0; o >>= 1) acc += __shfl_xor_sync(0xffffffffu, acc, o);
    if (lane == 0) s_wsum[wid] = acc;
    __syncthreads();
    if (tid == 0) {
        float s = 0.0f;
#pragma unroll
        for (int i = 0; i < 16; ++i) s += s_wsum[i];
        g_partial[blockIdx.x] = s;
        __threadfence();
        unsigned int ticket = atomicAdd(&g_count, 1u);
        s_last[0] = (ticket == 255u) ? 1 : 0;
    }
    __syncthreads();

    // ---- last block: deterministic finalize ----
    if (s_last[0]) {
        if (tid < 256) s_rd[tid] = (double)g_partial[tid];
        __syncthreads();
        for (int st = 128; st > 0; st >>= 1) {
            if (tid < st) s_rd[tid] += s_rd[tid + st];
            __syncthreads();
        }
        if (tid == 0) {
            if (loss_ptr) {
                float cl = (float)(s_rd[0] / (double)NQ_);
                loss_ptr[0] = __fadd_rn(cl, __fmul_rn(0.25f, cl));
            }
            g_count = 0;   // reset for next graph replay
        }
    }
}

// ---------------------------------------------------------------------------
extern "C" void kernel_launch(void* const* d_in, const int* in_sizes, int n_in,
                              void* d_out, int out_size) {
    const float* z  = nullptr;
    const float* cb = nullptr;
    for (int i = 0; i < n_in; ++i) {
        if (in_sizes[i] == NQ_)          z  = (const float*)d_in[i];
        else if (in_sizes[i] == K_ * D_) cb = (const float*)d_in[i];
    }
    if (!z || !cb) return;

    float* out = (float*)d_out;
    float* loss_ptr = nullptr;
    float* q_ptr    = nullptr;
    float* i_ptr    = nullptr;

    if (out_size == 1 + NQ_ + N_) {
        loss_ptr = out; q_ptr = out + 1; i_ptr = out + 1 + NQ_;
    } else if (out_size == NQ_ + N_) {
        q_ptr = out; i_ptr = out + NQ_;
    } else if (out_size == NQ_) {
        q_ptr = out;
    } else if (out_size == N_) {
        i_ptr = out;
    } else if (out_size == 1) {
        loss_ptr = out;
    } else if (out_size > 1 + NQ_ + N_) {
        loss_ptr = out; q_ptr = out + 1; i_ptr = out + 1 + NQ_;
    }

    static bool attr_done = false;
    if (!attr_done) {
        cudaFuncSetAttribute(vq_kernel,
                             cudaFuncAttributeMaxDynamicSharedMemorySize,
                             SM_TOT);
        attr_done = true;
    }

    prep_z_kernel<<<512, 256>>>(z);
    prep_cb1_kernel<<<2, 256>>>(cb);
    prep_cb2_kernel<<<2, 256>>>(cb);
    vq_kernel<<<N_ / 512, 512, SM_TOT>>>(z, cb, q_ptr, i_ptr, loss_ptr);
}